// round 4
// baseline (speedup 1.0000x reference)
#include <cuda_runtime.h>
#include <cstdint>

#define DEVINL static __device__ __forceinline__

// ---------------- problem dims ----------------
#define B_SZ   8192
#define KTOT   2048           // IN + H fused K
#define NOUT   4096           // 4 gates x 1024
#define NTHREADS 256
#define NSTAGE 4
#define NIT    64             // K / 32

// smem per stage: A 16KB (128 rows x 32 k) + B 32KB (256 cols x 32 k), fragment order
#define STAGE_BYTES (48 * 1024)
#define B_OFF       (16 * 1024)
#define SMEM_TOTAL  (NSTAGE * STAGE_BYTES)   // 196608

// scratch (device globals: allocation-free rule)
__device__ float4 g_A[(size_t)B_SZ * KTOT / 4];    // 64 MB, fragment-order [mb64][kt256][mt8][lane32]
__device__ float4 g_B[(size_t)NOUT * KTOT / 4];    // 32 MB, fragment-order [nb16][kt16_128][nt32][lane32]

// ---------------- helpers ----------------
DEVINL uint32_t smem_u32(const void* p){
  uint32_t a; asm("{ .reg .u64 t; cvta.to.shared.u64 t, %1; cvt.u32.u64 %0, t; }" : "=r"(a) : "l"(p)); return a;
}
DEVINL float tf32r(float f){ uint32_t r; asm("cvt.rna.tf32.f32 %0, %1;" : "=r"(r) : "f"(f)); return __uint_as_float(r); }
DEVINL void cp16(uint32_t dst, const void* src){
  asm volatile("cp.async.cg.shared.global [%0], [%1], 16;" :: "r"(dst), "l"(src));
}
DEVINL void cp_commit(){ asm volatile("cp.async.commit_group;"); }
template<int N> DEVINL void cp_wait(){ asm volatile("cp.async.wait_group %0;" :: "n"(N)); }

DEVINL void mma8(float* d, const uint4& a, uint32_t b0, uint32_t b1){
  asm volatile(
    "mma.sync.aligned.m16n8k8.row.col.f32.tf32.tf32.f32 "
    "{%0,%1,%2,%3}, {%4,%5,%6,%7}, {%8,%9}, {%0,%1,%2,%3};"
    : "+f"(d[0]), "+f"(d[1]), "+f"(d[2]), "+f"(d[3])
    : "r"(a.x), "r"(a.y), "r"(a.z), "r"(a.w), "r"(b0), "r"(b1));
}
DEVINL float sigmoidf_(float x){ return 1.f / (1.f + __expf(-x)); }

// ---------------- prep A ----------------
// Fragment layout: idx = ((mb*256 + kt8)*8 + mt)*32 + lane
//   thread(lane) float4 = { A[r][k], A[r+8][k], A[r][k+4], A[r+8][k+4] }
//   r = mb*128 + mt*16 + lane/4,  k = kt8*8 + lane%4,  A = [x | h]
__global__ void prep_A(const float* __restrict__ x, const float* __restrict__ h){
  size_t idx = (size_t)blockIdx.x * NTHREADS + threadIdx.x;   // [0, 4194304)
  int lane = (int)(idx & 31);
  int mt   = (int)((idx >> 5) & 7);
  int kt   = (int)((idx >> 8) & 255);
  int mb   = (int)(idx >> 16);
  int row = mb * 128 + mt * 16 + (lane >> 2);
  int k   = kt * 8 + (lane & 3);
  const float* src = (k < 1024) ? x : h;
  int ko = k & 1023;
  float4 v;
  v.x = tf32r(src[(size_t)row       * 1024 + ko]);
  v.y = tf32r(src[(size_t)(row + 8) * 1024 + ko]);
  v.z = tf32r(src[(size_t)row       * 1024 + ko + 4]);
  v.w = tf32r(src[(size_t)(row + 8) * 1024 + ko + 4]);
  g_A[idx] = v;
}

// ---------------- prep B ----------------
// Fragment layout: idx = ((nb*128 + kt16)*32 + nt)*32 + lane
//   nt encodes gate-interleave: g = nt&3, cb = nt>>2
//   logical W col n = g*1024 + nb*64 + cb*8 + lane/4,  k = kt16*16 + lane%4 + {0,4,8,12}
//   thread float4 = { W[k][n], W[k+4][n], W[k+8][n], W[k+12][n] }   (W = [Wx ; Wh])
__global__ void prep_B(const float* __restrict__ Wx, const float* __restrict__ Wh){
  size_t idx = (size_t)blockIdx.x * NTHREADS + threadIdx.x;   // [0, 2097152)
  int lane = (int)(idx & 31);
  int nt   = (int)((idx >> 5) & 31);
  int kt16 = (int)((idx >> 10) & 127);
  int nb   = (int)(idx >> 17);
  int g = nt & 3, cb = nt >> 2;
  int n  = g * 1024 + nb * 64 + cb * 8 + (lane >> 2);
  int k0 = kt16 * 16 + (lane & 3);
  const float* W = (k0 < 1024) ? Wx : Wh;
  int k = k0 & 1023;
  float4 v;
  v.x = tf32r(W[(size_t)k        * 4096 + n]);
  v.y = tf32r(W[(size_t)(k + 4)  * 4096 + n]);
  v.z = tf32r(W[(size_t)(k + 8)  * 4096 + n]);
  v.w = tf32r(W[(size_t)(k + 12) * 4096 + n]);
  g_B[idx] = v;
}

// ---------------- main fused GEMM + LSTM ----------------
__global__ void __launch_bounds__(NTHREADS, 1)
lstm_main(const float* __restrict__ c,
          const float* __restrict__ bx, const float* __restrict__ bh,
          float* __restrict__ out)
{
  extern __shared__ char smem[];
  const uint32_t sb = smem_u32(smem);
  const int tid = threadIdx.x;
  const int w   = tid >> 5;
  const int T   = tid & 31;
  const int w_m = w >> 2;          // 0..1 (64 rows each)
  const int w_n = w & 3;           // 0..3 (8 nt tiles each)
  const int nb  = blockIdx.x;      // 16
  const int mb  = blockIdx.y;      // 64

  const float4* gA = g_A + (size_t)mb * 65536;    // 1024 float4 per stage, linear
  const float4* gB = g_B + (size_t)nb * 131072;   // 2048 float4 per stage, linear

  auto load_stage = [&](int st){
    uint32_t base = sb + (st & (NSTAGE - 1)) * STAGE_BYTES;
    const float4* srcA = gA + (size_t)st * 1024;
    #pragma unroll
    for (int i = 0; i < 4; ++i)
      cp16(base + (tid + i * NTHREADS) * 16, srcA + tid + i * NTHREADS);
    const float4* srcB = gB + (size_t)st * 2048;
    #pragma unroll
    for (int i = 0; i < 8; ++i)
      cp16(base + B_OFF + (tid + i * NTHREADS) * 16, srcB + tid + i * NTHREADS);
  };

  float acc[4][8][4];
  #pragma unroll
  for (int a = 0; a < 4; ++a)
    #pragma unroll
    for (int b = 0; b < 8; ++b)
      #pragma unroll
      for (int q = 0; q < 4; ++q) acc[a][b][q] = 0.f;

  // prologue: 3 stages in flight
  load_stage(0); cp_commit();
  load_stage(1); cp_commit();
  load_stage(2); cp_commit();

  for (int st = 0; st < NIT; ++st){
    cp_wait<NSTAGE - 2>();
    __syncthreads();
    // keep commit-group accounting aligned even when no loads remain
    if (st + 3 < NIT) load_stage(st + 3);
    cp_commit();

    const uint4* As = (const uint4*)(smem + (st & (NSTAGE - 1)) * STAGE_BYTES);
    const uint4* Bs = (const uint4*)(smem + (st & (NSTAGE - 1)) * STAGE_BYTES + B_OFF);

    #pragma unroll
    for (int ks16 = 0; ks16 < 2; ++ks16){
      uint4 bf[8];
      #pragma unroll
      for (int j = 0; j < 8; ++j)
        bf[j] = Bs[(ks16 * 32 + w_n * 8 + j) * 32 + T];
      #pragma unroll
      for (int half = 0; half < 2; ++half){
        uint4 af[4];
        #pragma unroll
        for (int mt = 0; mt < 4; ++mt)
          af[mt] = As[((ks16 * 2 + half) * 8 + w_m * 4 + mt) * 32 + T];
        #pragma unroll
        for (int mt = 0; mt < 4; ++mt)
          #pragma unroll
          for (int j = 0; j < 8; ++j){
            uint32_t b0 = half ? bf[j].z : bf[j].x;
            uint32_t b1 = half ? bf[j].w : bf[j].y;
            mma8(acc[mt][j], af[mt], b0, b1);
          }
      }
    }
  }

  // -------- fused LSTM epilogue (all register-local: gates g at acc[.][jc*4+g]) --------
  const size_t S = (size_t)B_SZ * 1024;

  // biases per (jc, gate, cc)
  float bias[2][4][2];
  #pragma unroll
  for (int jc = 0; jc < 2; ++jc){
    int col = nb * 64 + (w_n * 2 + jc) * 8 + (T & 3) * 2;
    #pragma unroll
    for (int g = 0; g < 4; ++g)
      #pragma unroll
      for (int cc = 0; cc < 2; ++cc)
        bias[jc][g][cc] = bx[g * 1024 + col + cc] + bh[g * 1024 + col + cc];
  }

  #pragma unroll
  for (int mt = 0; mt < 4; ++mt){
    #pragma unroll
    for (int jc = 0; jc < 2; ++jc){
      int col = nb * 64 + (w_n * 2 + jc) * 8 + (T & 3) * 2;
      #pragma unroll
      for (int rr = 0; rr < 2; ++rr){
        int row = mb * 128 + w_m * 64 + mt * 16 + (T >> 2) + rr * 8;
        size_t ro = (size_t)row * 1024 + col;
        float2 cin = *(const float2*)(c + ro);
        float2 o2, h2, c2;
        #pragma unroll
        for (int cc = 0; cc < 2; ++cc){
          int q = rr * 2 + cc;
          float vi = acc[mt][jc * 4 + 0][q] + bias[jc][0][cc];
          float vf = acc[mt][jc * 4 + 1][q] + bias[jc][1][cc];
          float vg = acc[mt][jc * 4 + 2][q] + bias[jc][2][cc];
          float vo = acc[mt][jc * 4 + 3][q] + bias[jc][3][cc];
          float ig = sigmoidf_(vi);
          float fg = sigmoidf_(vf);
          float gg = tanhf(vg);
          float og = sigmoidf_(vo);
          float cv = (cc == 0) ? cin.x : cin.y;
          float cn = fg * cv + ig * gg;
          float hn = og * tanhf(cn);
          if (cc == 0){ o2.x = og; h2.x = hn; c2.x = cn; }
          else        { o2.y = og; h2.y = hn; c2.y = cn; }
        }
        *(float2*)(out + ro)         = o2;   // output gate
        *(float2*)(out + S + ro)     = h2;   // h_new
        *(float2*)(out + 2 * S + ro) = c2;   // c_new
      }
    }
  }
}

// ---------------- launch ----------------
extern "C" void kernel_launch(void* const* d_in, const int* in_sizes, int n_in,
                              void* d_out, int out_size)
{
  const float* x  = (const float*)d_in[0];
  const float* h  = (const float*)d_in[1];
  const float* c  = (const float*)d_in[2];
  const float* Wx = (const float*)d_in[3];
  const float* Wh = (const float*)d_in[4];
  const float* bx = (const float*)d_in[5];
  const float* bh = (const float*)d_in[6];
  float* out = (float*)d_out;

  cudaFuncSetAttribute(lstm_main,
                       cudaFuncAttributeMaxDynamicSharedMemorySize, SMEM_TOTAL);

  prep_A<<<(B_SZ * KTOT / 4) / NTHREADS, NTHREADS>>>(x, h);          // 16384 blocks
  prep_B<<<(NOUT * KTOT / 4) / NTHREADS, NTHREADS>>>(Wx, Wh);        //  8192 blocks
  lstm_main<<<dim3(16, 64), NTHREADS, SMEM_TOTAL>>>(c, bx, bh, out);
}

// round 6
// speedup vs baseline: 1.7048x; 1.7048x over previous
#include <cuda_runtime.h>
#include <cuda_fp16.h>
#include <cstdint>

#define DEVINL static __device__ __forceinline__

// ---------------- problem dims ----------------
#define B_SZ   8192
#define KTOT   2048           // IN + H fused K
#define NOUT   4096           // 4 gates x 1024
#define NTHREADS 256
#define NSTAGE 4
#define NIT    32             // K / 64 per stage

// smem per stage: A 128 rows x 64 k x fp16 = 16KB, B 256 cols x 64 k x fp16 = 32KB
#define STAGE_BYTES (48 * 1024)
#define B_OFF       (16 * 1024)
#define SMEM_TOTAL  (NSTAGE * STAGE_BYTES)   // 196608

// scratch (device globals: allocation-free rule), fp16 fragment-order
__device__ uint4 g_A[(size_t)B_SZ * KTOT / 8];     // 32 MB  [mb64][kt16_128][mt8][lane32]
__device__ uint2 g_B[(size_t)NOUT * KTOT / 4];     // 16 MB  [nb16][kt16_128][nt32][lane32]

// ---------------- helpers ----------------
DEVINL uint32_t smem_u32(const void* p){
  uint32_t a; asm("{ .reg .u64 t; cvta.to.shared.u64 t, %1; cvt.u32.u64 %0, t; }" : "=r"(a) : "l"(p)); return a;
}
DEVINL void cp16(uint32_t dst, const void* src){
  asm volatile("cp.async.cg.shared.global [%0], [%1], 16;" :: "r"(dst), "l"(src));
}
DEVINL void cp_commit(){ asm volatile("cp.async.commit_group;"); }
template<int N> DEVINL void cp_wait(){ asm volatile("cp.async.wait_group %0;" :: "n"(N)); }

DEVINL void mma16(float* d, const uint4& a, uint32_t b0, uint32_t b1){
  asm volatile(
    "mma.sync.aligned.m16n8k16.row.col.f32.f16.f16.f32 "
    "{%0,%1,%2,%3}, {%4,%5,%6,%7}, {%8,%9}, {%0,%1,%2,%3};"
    : "+f"(d[0]), "+f"(d[1]), "+f"(d[2]), "+f"(d[3])
    : "r"(a.x), "r"(a.y), "r"(a.z), "r"(a.w), "r"(b0), "r"(b1));
}
DEVINL float sigmoidf_(float x){ return 1.f / (1.f + __expf(-x)); }
DEVINL uint32_t pack2(float lo, float hi){
  __half2 v = __floats2half2_rn(lo, hi);
  return *reinterpret_cast<uint32_t*>(&v);
}

// ---------------- prep A ----------------
// m16n8k16 A-fragment order: idx = ((mb*128 + kt16)*8 + mt)*32 + lane
//   r = mb*128 + mt*16 + lane/4,  k = kt16*16 + (lane%4)*2,  A = [x | h]
//   uint4 = { h2(A[r][k],A[r][k+1]), h2(A[r+8][k],A[r+8][k+1]),
//             h2(A[r][k+8],A[r][k+9]), h2(A[r+8][k+8],A[r+8][k+9]) }
__global__ void prep_A(const float* __restrict__ x, const float* __restrict__ h){
  size_t idx = (size_t)blockIdx.x * NTHREADS + threadIdx.x;   // [0, 2097152)
  int lane = (int)(idx & 31);
  int mt   = (int)((idx >> 5) & 7);
  int kt   = (int)((idx >> 8) & 127);
  int mb   = (int)(idx >> 15);
  int r = mb * 128 + mt * 16 + (lane >> 2);
  int k = kt * 16 + (lane & 3) * 2;
  const float* src = (k < 1024) ? x : h;
  int ko = k & 1023;
  const float* p0 = src + (size_t)r * 1024 + ko;
  const float* p1 = src + (size_t)(r + 8) * 1024 + ko;
  uint4 v;
  v.x = pack2(p0[0], p0[1]);
  v.y = pack2(p1[0], p1[1]);
  v.z = pack2(p0[8], p0[9]);
  v.w = pack2(p1[8], p1[9]);
  g_A[idx] = v;
}

// ---------------- prep B ----------------
// m16n8k16 B-fragment order: idx = ((nb*128 + kt16)*32 + nt)*32 + lane
//   gate interleave: g = nt&3, cb = nt>>2
//   n = g*1024 + nb*64 + cb*8 + lane/4,  k = kt16*16 + (lane%4)*2,  W = [Wx ; Wh]
//   uint2 = { h2(W[k][n],W[k+1][n]), h2(W[k+8][n],W[k+9][n]) }
__global__ void prep_B(const float* __restrict__ Wx, const float* __restrict__ Wh){
  size_t idx = (size_t)blockIdx.x * NTHREADS + threadIdx.x;   // [0, 2097152)
  int lane = (int)(idx & 31);
  int nt   = (int)((idx >> 5) & 31);
  int kt   = (int)((idx >> 10) & 127);
  int nb   = (int)(idx >> 17);
  int g = nt & 3, cb = nt >> 2;
  int n  = g * 1024 + nb * 64 + cb * 8 + (lane >> 2);
  int k0 = kt * 16 + (lane & 3) * 2;
  const float* W = (k0 < 1024) ? Wx : Wh;
  int k = k0 & 1023;
  uint2 v;
  v.x = pack2(W[(size_t)k       * 4096 + n], W[(size_t)(k + 1) * 4096 + n]);
  v.y = pack2(W[(size_t)(k + 8) * 4096 + n], W[(size_t)(k + 9) * 4096 + n]);
  g_B[idx] = v;
}

// ---------------- main fused GEMM + LSTM ----------------
__global__ void __launch_bounds__(NTHREADS, 1)
lstm_main(const float* __restrict__ c,
          const float* __restrict__ bx, const float* __restrict__ bh,
          float* __restrict__ out)
{
  extern __shared__ char smem[];
  const uint32_t sb = smem_u32(smem);
  const int tid = threadIdx.x;
  const int w   = tid >> 5;
  const int T   = tid & 31;
  const int w_m = w >> 2;          // 0..1 (64 rows each)
  const int w_n = w & 3;           // 0..3 (8 nt tiles each)
  const int nb  = blockIdx.x;      // 16
  const int mb  = blockIdx.y;      // 64

  // per-CTA bases; per stage (4 kt16): A = 1024 uint4, B = 4096 uint2 (contiguous)
  const uint4* gA = g_A + (size_t)mb * (128 * 8 * 32 / 8) * 8;   // mb * 32768 uint4
  const uint2* gB = g_B + (size_t)nb * 131072;                   // nb * 131072 uint2

  auto load_stage = [&](int st){
    uint32_t base = sb + (st & (NSTAGE - 1)) * STAGE_BYTES;
    const uint4* srcA = gA + (size_t)st * 1024;
    #pragma unroll
    for (int i = 0; i < 4; ++i)
      cp16(base + (tid + i * NTHREADS) * 16, srcA + tid + i * NTHREADS);
    const uint2* srcB = gB + (size_t)st * 4096;
    #pragma unroll
    for (int i = 0; i < 8; ++i)
      cp16(base + B_OFF + (tid + i * NTHREADS) * 16, srcB + 2 * (tid + i * NTHREADS));
  };

  float acc[4][8][4];
  #pragma unroll
  for (int a = 0; a < 4; ++a)
    #pragma unroll
    for (int b = 0; b < 8; ++b)
      #pragma unroll
      for (int q = 0; q < 4; ++q) acc[a][b][q] = 0.f;

  // prologue: 3 stages in flight
  load_stage(0); cp_commit();
  load_stage(1); cp_commit();
  load_stage(2); cp_commit();

  for (int st = 0; st < NIT; ++st){
    cp_wait<NSTAGE - 2>();
    __syncthreads();
    // keep commit-group accounting aligned even when no loads remain
    if (st + 3 < NIT) load_stage(st + 3);
    cp_commit();

    const uint4* As = (const uint4*)(smem + (st & (NSTAGE - 1)) * STAGE_BYTES);
    const uint2* Bs = (const uint2*)(smem + (st & (NSTAGE - 1)) * STAGE_BYTES + B_OFF);

    #pragma unroll
    for (int kt = 0; kt < 4; ++kt){
      uint2 bf[8];
      #pragma unroll
      for (int j = 0; j < 8; ++j)
        bf[j] = Bs[(kt * 32 + w_n * 8 + j) * 32 + T];
      uint4 af[4];
      #pragma unroll
      for (int mt = 0; mt < 4; ++mt)
        af[mt] = As[(kt * 8 + w_m * 4 + mt) * 32 + T];
      #pragma unroll
      for (int mt = 0; mt < 4; ++mt)
        #pragma unroll
        for (int j = 0; j < 8; ++j)
          mma16(acc[mt][j], af[mt], bf[j].x, bf[j].y);
    }
  }

  // -------- fused LSTM epilogue (register-local: gates g at acc[.][jc*4+g]) --------
  const size_t S = (size_t)B_SZ * 1024;

  float bias[2][4][2];
  #pragma unroll
  for (int jc = 0; jc < 2; ++jc){
    int col = nb * 64 + (w_n * 2 + jc) * 8 + (T & 3) * 2;
    #pragma unroll
    for (int g = 0; g < 4; ++g)
      #pragma unroll
      for (int cc = 0; cc < 2; ++cc)
        bias[jc][g][cc] = bx[g * 1024 + col + cc] + bh[g * 1024 + col + cc];
  }

  #pragma unroll
  for (int mt = 0; mt < 4; ++mt){
    #pragma unroll
    for (int jc = 0; jc < 2; ++jc){
      int col = nb * 64 + (w_n * 2 + jc) * 8 + (T & 3) * 2;
      #pragma unroll
      for (int rr = 0; rr < 2; ++rr){
        int row = mb * 128 + w_m * 64 + mt * 16 + (T >> 2) + rr * 8;
        size_t ro = (size_t)row * 1024 + col;
        float2 cin = *(const float2*)(c + ro);
        float2 o2, h2v, c2;
        #pragma unroll
        for (int cc = 0; cc < 2; ++cc){
          int q = rr * 2 + cc;
          float vi = acc[mt][jc * 4 + 0][q] + bias[jc][0][cc];
          float vf = acc[mt][jc * 4 + 1][q] + bias[jc][1][cc];
          float vg = acc[mt][jc * 4 + 2][q] + bias[jc][2][cc];
          float vo = acc[mt][jc * 4 + 3][q] + bias[jc][3][cc];
          float ig = sigmoidf_(vi);
          float fg = sigmoidf_(vf);
          float gg = tanhf(vg);
          float og = sigmoidf_(vo);
          float cv = (cc == 0) ? cin.x : cin.y;
          float cn = fg * cv + ig * gg;
          float hn = og * tanhf(cn);
          if (cc == 0){ o2.x = og; h2v.x = hn; c2.x = cn; }
          else        { o2.y = og; h2v.y = hn; c2.y = cn; }
        }
        *(float2*)(out + ro)         = o2;    // output gate
        *(float2*)(out + S + ro)     = h2v;   // h_new
        *(float2*)(out + 2 * S + ro) = c2;    // c_new
      }
    }
  }
}

// ---------------- launch ----------------
extern "C" void kernel_launch(void* const* d_in, const int* in_sizes, int n_in,
                              void* d_out, int out_size)
{
  const float* x  = (const float*)d_in[0];
  const float* h  = (const float*)d_in[1];
  const float* c  = (const float*)d_in[2];
  const float* Wx = (const float*)d_in[3];
  const float* Wh = (const float*)d_in[4];
  const float* bx = (const float*)d_in[5];
  const float* bh = (const float*)d_in[6];
  float* out = (float*)d_out;

  cudaFuncSetAttribute(lstm_main,
                       cudaFuncAttributeMaxDynamicSharedMemorySize, SMEM_TOTAL);

  prep_A<<<(B_SZ * KTOT / 8) / NTHREADS, NTHREADS>>>(x, h);          // 8192 blocks
  prep_B<<<(NOUT * KTOT / 4) / NTHREADS, NTHREADS>>>(Wx, Wh);        // 8192 blocks
  lstm_main<<<dim3(16, 64), NTHREADS, SMEM_TOTAL>>>(c, bx, bh, out);
}

// round 7
// speedup vs baseline: 1.7421x; 1.0219x over previous
#include <cuda_runtime.h>
#include <cuda_fp16.h>
#include <cstdint>

#define DEVINL static __device__ __forceinline__

// ---------------- problem dims ----------------
#define B_SZ   8192
#define KTOT   2048           // IN + H fused K
#define NOUT   4096           // 4 gates x 1024
#define NTHREADS 512
#define NSTAGE 4
#define NIT    32             // K / 64 per stage

// smem per stage: A 128 rows x 64 k x fp16 = 16KB, B 256 cols x 64 k x fp16 = 32KB
#define STAGE_BYTES (48 * 1024)
#define B_OFF       (16 * 1024)
#define SMEM_TOTAL  (NSTAGE * STAGE_BYTES)   // 196608

// scratch (device globals: allocation-free rule), fp16 fragment-order
__device__ uint4 g_A[(size_t)B_SZ * KTOT / 8];     // 32 MB  [mb64][kt16_128][mt8][lane32]
__device__ uint2 g_B[(size_t)NOUT * KTOT / 4];     // 16 MB  [nb16][kt16_128][nt32][lane32]

// ---------------- helpers ----------------
DEVINL uint32_t smem_u32(const void* p){
  uint32_t a; asm("{ .reg .u64 t; cvta.to.shared.u64 t, %1; cvt.u32.u64 %0, t; }" : "=r"(a) : "l"(p)); return a;
}
DEVINL void cp16(uint32_t dst, const void* src){
  asm volatile("cp.async.cg.shared.global [%0], [%1], 16;" :: "r"(dst), "l"(src));
}
DEVINL void cp_commit(){ asm volatile("cp.async.commit_group;"); }
template<int N> DEVINL void cp_wait(){ asm volatile("cp.async.wait_group %0;" :: "n"(N)); }

DEVINL void mma16(float* d, const uint4& a, uint32_t b0, uint32_t b1){
  asm volatile(
    "mma.sync.aligned.m16n8k16.row.col.f32.f16.f16.f32 "
    "{%0,%1,%2,%3}, {%4,%5,%6,%7}, {%8,%9}, {%0,%1,%2,%3};"
    : "+f"(d[0]), "+f"(d[1]), "+f"(d[2]), "+f"(d[3])
    : "r"(a.x), "r"(a.y), "r"(a.z), "r"(a.w), "r"(b0), "r"(b1));
}
DEVINL float sigmoidf_(float x){ return 1.f / (1.f + __expf(-x)); }
DEVINL uint32_t pack2(float lo, float hi){
  __half2 v = __floats2half2_rn(lo, hi);
  return *reinterpret_cast<uint32_t*>(&v);
}

// ---------------- prep A ----------------
// m16n8k16 A-fragment order: idx = ((mb*128 + kt16)*8 + mt)*32 + lane
//   r = mb*128 + mt*16 + lane/4,  k = kt16*16 + (lane%4)*2,  A = [x | h]
//   uint4 = { h2(A[r][k],A[r][k+1]), h2(A[r+8][k],A[r+8][k+1]),
//             h2(A[r][k+8],A[r][k+9]), h2(A[r+8][k+8],A[r+8][k+9]) }
__global__ void prep_A(const float* __restrict__ x, const float* __restrict__ h){
  size_t idx = (size_t)blockIdx.x * 256 + threadIdx.x;   // [0, 2097152)
  int lane = (int)(idx & 31);
  int mt   = (int)((idx >> 5) & 7);
  int kt   = (int)((idx >> 8) & 127);
  int mb   = (int)(idx >> 15);
  int r = mb * 128 + mt * 16 + (lane >> 2);
  int k = kt * 16 + (lane & 3) * 2;
  const float* src = (k < 1024) ? x : h;
  int ko = k & 1023;
  const float* p0 = src + (size_t)r * 1024 + ko;
  const float* p1 = src + (size_t)(r + 8) * 1024 + ko;
  uint4 v;
  v.x = pack2(p0[0], p0[1]);
  v.y = pack2(p1[0], p1[1]);
  v.z = pack2(p0[8], p0[9]);
  v.w = pack2(p1[8], p1[9]);
  g_A[idx] = v;
}

// ---------------- prep B ----------------
// m16n8k16 B-fragment order: idx = ((nb*128 + kt16)*32 + nt)*32 + lane
//   gate interleave: g = nt&3, cb = nt>>2
//   n = g*1024 + nb*64 + cb*8 + lane/4,  k = kt16*16 + (lane%4)*2,  W = [Wx ; Wh]
//   uint2 = { h2(W[k][n],W[k+1][n]), h2(W[k+8][n],W[k+9][n]) }
__global__ void prep_B(const float* __restrict__ Wx, const float* __restrict__ Wh){
  size_t idx = (size_t)blockIdx.x * 256 + threadIdx.x;   // [0, 2097152)
  int lane = (int)(idx & 31);
  int nt   = (int)((idx >> 5) & 31);
  int kt   = (int)((idx >> 10) & 127);
  int nb   = (int)(idx >> 17);
  int g = nt & 3, cb = nt >> 2;
  int n  = g * 1024 + nb * 64 + cb * 8 + (lane >> 2);
  int k0 = kt * 16 + (lane & 3) * 2;
  const float* W = (k0 < 1024) ? Wx : Wh;
  int k = k0 & 1023;
  uint2 v;
  v.x = pack2(W[(size_t)k       * 4096 + n], W[(size_t)(k + 1) * 4096 + n]);
  v.y = pack2(W[(size_t)(k + 8) * 4096 + n], W[(size_t)(k + 9) * 4096 + n]);
  g_B[idx] = v;
}

// ---------------- main fused GEMM + LSTM ----------------
// 512 threads = 16 warps as 4x4 grid; warp tile 32 rows x 64 permuted cols
__global__ void __launch_bounds__(NTHREADS, 1)
lstm_main(const float* __restrict__ c,
          const float* __restrict__ bx, const float* __restrict__ bh,
          float* __restrict__ out)
{
  extern __shared__ char smem[];
  const int tid = threadIdx.x;
  const int w   = tid >> 5;
  const int T   = tid & 31;
  const int w_m = w >> 2;          // 0..3 (32 rows each)
  const int w_n = w & 3;           // 0..3 (8 nt tiles each)
  const int nb  = blockIdx.x;      // 16
  const int mb  = blockIdx.y;      // 64

  // per-CTA bases; per stage (4 kt16): A = 1024 uint4, B = 4096 uint2 (contiguous)
  const uint4* gA = g_A + (size_t)mb * 32768;
  const uint2* gB = g_B + (size_t)nb * 131072;

  auto load_stage = [&](int st){
    uint32_t base = smem_u32(smem) + (st & (NSTAGE - 1)) * STAGE_BYTES;
    const uint4* srcA = gA + (size_t)st * 1024;
    #pragma unroll
    for (int i = 0; i < 2; ++i)
      cp16(base + (tid + i * NTHREADS) * 16, srcA + tid + i * NTHREADS);
    const uint2* srcB = gB + (size_t)st * 4096;
    #pragma unroll
    for (int i = 0; i < 4; ++i)
      cp16(base + B_OFF + (tid + i * NTHREADS) * 16, srcB + 2 * (tid + i * NTHREADS));
  };

  float acc[2][8][4];
  #pragma unroll
  for (int a = 0; a < 2; ++a)
    #pragma unroll
    for (int b = 0; b < 8; ++b)
      #pragma unroll
      for (int q = 0; q < 4; ++q) acc[a][b][q] = 0.f;

  // prologue: 3 stages in flight
  load_stage(0); cp_commit();
  load_stage(1); cp_commit();
  load_stage(2); cp_commit();

  for (int st = 0; st < NIT; ++st){
    cp_wait<NSTAGE - 2>();
    __syncthreads();
    // after this sync all warps finished computing stage st-1, whose buffer
    // (st+3)&3 we now overwrite
    if (st + 3 < NIT) load_stage(st + 3);
    cp_commit();

    const uint4* As = (const uint4*)(smem + (st & (NSTAGE - 1)) * STAGE_BYTES);
    const uint2* Bs = (const uint2*)(smem + (st & (NSTAGE - 1)) * STAGE_BYTES + B_OFF);

    #pragma unroll
    for (int kt = 0; kt < 4; ++kt){
      uint2 bf[8];
      #pragma unroll
      for (int j = 0; j < 8; ++j)
        bf[j] = Bs[(kt * 32 + w_n * 8 + j) * 32 + T];
      uint4 af[2];
      #pragma unroll
      for (int mt = 0; mt < 2; ++mt)
        af[mt] = As[(kt * 8 + w_m * 2 + mt) * 32 + T];
      #pragma unroll
      for (int mt = 0; mt < 2; ++mt)
        #pragma unroll
        for (int j = 0; j < 8; ++j)
          mma16(acc[mt][j], af[mt], bf[j].x, bf[j].y);
    }
  }

  // -------- fused LSTM epilogue (register-local: gates g at acc[.][jc*4+g]) --------
  const size_t S = (size_t)B_SZ * 1024;

  float bias[2][4][2];
  #pragma unroll
  for (int jc = 0; jc < 2; ++jc){
    int col = nb * 64 + (w_n * 2 + jc) * 8 + (T & 3) * 2;
    #pragma unroll
    for (int g = 0; g < 4; ++g)
      #pragma unroll
      for (int cc = 0; cc < 2; ++cc)
        bias[jc][g][cc] = bx[g * 1024 + col + cc] + bh[g * 1024 + col + cc];
  }

  #pragma unroll
  for (int mt = 0; mt < 2; ++mt){
    #pragma unroll
    for (int jc = 0; jc < 2; ++jc){
      int col = nb * 64 + (w_n * 2 + jc) * 8 + (T & 3) * 2;
      #pragma unroll
      for (int rr = 0; rr < 2; ++rr){
        int row = mb * 128 + w_m * 32 + mt * 16 + (T >> 2) + rr * 8;
        size_t ro = (size_t)row * 1024 + col;
        float2 cin = *(const float2*)(c + ro);
        float2 o2, h2v, c2;
        #pragma unroll
        for (int cc = 0; cc < 2; ++cc){
          int q = rr * 2 + cc;
          float vi = acc[mt][jc * 4 + 0][q] + bias[jc][0][cc];
          float vf = acc[mt][jc * 4 + 1][q] + bias[jc][1][cc];
          float vg = acc[mt][jc * 4 + 2][q] + bias[jc][2][cc];
          float vo = acc[mt][jc * 4 + 3][q] + bias[jc][3][cc];
          float ig = sigmoidf_(vi);
          float fg = sigmoidf_(vf);
          float gg = tanhf(vg);
          float og = sigmoidf_(vo);
          float cv = (cc == 0) ? cin.x : cin.y;
          float cn = fg * cv + ig * gg;
          float hn = og * tanhf(cn);
          if (cc == 0){ o2.x = og; h2v.x = hn; c2.x = cn; }
          else        { o2.y = og; h2v.y = hn; c2.y = cn; }
        }
        *(float2*)(out + ro)         = o2;    // output gate
        *(float2*)(out + S + ro)     = h2v;   // h_new
        *(float2*)(out + 2 * S + ro) = c2;    // c_new
      }
    }
  }
}

// ---------------- launch ----------------
extern "C" void kernel_launch(void* const* d_in, const int* in_sizes, int n_in,
                              void* d_out, int out_size)
{
  const float* x  = (const float*)d_in[0];
  const float* h  = (const float*)d_in[1];
  const float* c  = (const float*)d_in[2];
  const float* Wx = (const float*)d_in[3];
  const float* Wh = (const float*)d_in[4];
  const float* bx = (const float*)d_in[5];
  const float* bh = (const float*)d_in[6];
  float* out = (float*)d_out;

  cudaFuncSetAttribute(lstm_main,
                       cudaFuncAttributeMaxDynamicSharedMemorySize, SMEM_TOTAL);

  prep_A<<<(B_SZ * KTOT / 8) / 256, 256>>>(x, h);          // 8192 blocks
  prep_B<<<(NOUT * KTOT / 4) / 256, 256>>>(Wx, Wh);        // 8192 blocks
  lstm_main<<<dim3(16, 64), NTHREADS, SMEM_TOTAL>>>(c, bx, bh, out);
}

// round 8
// speedup vs baseline: 2.0354x; 1.1683x over previous
#include <cuda_runtime.h>
#include <cuda_fp16.h>
#include <cstdint>

#define DEVINL static __device__ __forceinline__

// ---------------- problem dims ----------------
#define B_SZ   8192
#define KTOT   2048           // IN + H fused K
#define NOUT   4096           // 4 gates x 1024
#define NTHREADS 512
#define NSTAGE 2
#define KSTAGE 128            // K per stage
#define NIT    (KTOT / KSTAGE)   // 16

// smem per stage: A 128 rows x 128 k x fp16 = 32KB, B 256 cols x 128 k x fp16 = 64KB
#define STAGE_BYTES (96 * 1024)
#define B_OFF       (32 * 1024)
#define SMEM_TOTAL  (NSTAGE * STAGE_BYTES)   // 196608

// scratch (device globals: allocation-free rule), fp16 fragment-order
__device__ uint4 g_A[(size_t)B_SZ * KTOT / 8];     // 32 MB  [mb64][kt16_128][mt8][lane32]
__device__ uint2 g_B[(size_t)NOUT * KTOT / 4];     // 16 MB  [nb16][kt16_128][nt32][lane32]

// ---------------- helpers ----------------
DEVINL uint32_t smem_u32(const void* p){
  uint32_t a; asm("{ .reg .u64 t; cvta.to.shared.u64 t, %1; cvt.u32.u64 %0, t; }" : "=r"(a) : "l"(p)); return a;
}
DEVINL void cp16(uint32_t dst, const void* src){
  asm volatile("cp.async.cg.shared.global [%0], [%1], 16;" :: "r"(dst), "l"(src));
}
DEVINL void cp_commit(){ asm volatile("cp.async.commit_group;"); }
template<int N> DEVINL void cp_wait(){ asm volatile("cp.async.wait_group %0;" :: "n"(N)); }

DEVINL void mma16(float* d, const uint4& a, uint32_t b0, uint32_t b1){
  asm volatile(
    "mma.sync.aligned.m16n8k16.row.col.f32.f16.f16.f32 "
    "{%0,%1,%2,%3}, {%4,%5,%6,%7}, {%8,%9}, {%0,%1,%2,%3};"
    : "+f"(d[0]), "+f"(d[1]), "+f"(d[2]), "+f"(d[3])
    : "r"(a.x), "r"(a.y), "r"(a.z), "r"(a.w), "r"(b0), "r"(b1));
}
DEVINL float sigmoidf_(float x){ return 1.f / (1.f + __expf(-x)); }
DEVINL uint32_t pack2(float lo, float hi){
  __half2 v = __floats2half2_rn(lo, hi);
  return *reinterpret_cast<uint32_t*>(&v);
}

// ---------------- prep A ----------------
// m16n8k16 A-fragment order: idx = ((mb*128 + kt16)*8 + mt)*32 + lane
//   r = mb*128 + mt*16 + lane/4,  k = kt16*16 + (lane%4)*2,  A = [x | h]
__global__ void prep_A(const float* __restrict__ x, const float* __restrict__ h){
  size_t idx = (size_t)blockIdx.x * 256 + threadIdx.x;   // [0, 2097152)
  int lane = (int)(idx & 31);
  int mt   = (int)((idx >> 5) & 7);
  int kt   = (int)((idx >> 8) & 127);
  int mb   = (int)(idx >> 15);
  int r = mb * 128 + mt * 16 + (lane >> 2);
  int k = kt * 16 + (lane & 3) * 2;
  const float* src = (k < 1024) ? x : h;
  int ko = k & 1023;
  const float* p0 = src + (size_t)r * 1024 + ko;
  const float* p1 = src + (size_t)(r + 8) * 1024 + ko;
  uint4 v;
  v.x = pack2(p0[0], p0[1]);
  v.y = pack2(p1[0], p1[1]);
  v.z = pack2(p0[8], p0[9]);
  v.w = pack2(p1[8], p1[9]);
  g_A[idx] = v;
}

// ---------------- prep B ----------------
// m16n8k16 B-fragment order: idx = ((nb*128 + kt16)*32 + nt)*32 + lane
//   gate interleave: g = nt&3, cb = nt>>2
//   n = g*1024 + nb*64 + cb*8 + lane/4,  k = kt16*16 + (lane%4)*2,  W = [Wx ; Wh]
__global__ void prep_B(const float* __restrict__ Wx, const float* __restrict__ Wh){
  size_t idx = (size_t)blockIdx.x * 256 + threadIdx.x;   // [0, 2097152)
  int lane = (int)(idx & 31);
  int nt   = (int)((idx >> 5) & 31);
  int kt   = (int)((idx >> 10) & 127);
  int nb   = (int)(idx >> 17);
  int g = nt & 3, cb = nt >> 2;
  int n  = g * 1024 + nb * 64 + cb * 8 + (lane >> 2);
  int k0 = kt * 16 + (lane & 3) * 2;
  const float* W = (k0 < 1024) ? Wx : Wh;
  int k = k0 & 1023;
  uint2 v;
  v.x = pack2(W[(size_t)k       * 4096 + n], W[(size_t)(k + 1) * 4096 + n]);
  v.y = pack2(W[(size_t)(k + 8) * 4096 + n], W[(size_t)(k + 9) * 4096 + n]);
  g_B[idx] = v;
}

// ---------------- main fused GEMM + LSTM ----------------
// 512 threads = 16 warps as 4x4 grid; warp tile 32 rows x 64 permuted cols
// 2-stage ring, K=128/stage, cp.async spread through the MMA loop.
__global__ void __launch_bounds__(NTHREADS, 1)
lstm_main(const float* __restrict__ c,
          const float* __restrict__ bx, const float* __restrict__ bh,
          float* __restrict__ out)
{
  extern __shared__ char smem[];
  const uint32_t sb = smem_u32(smem);
  const int tid = threadIdx.x;
  const int w   = tid >> 5;
  const int T   = tid & 31;
  const int w_m = w >> 2;          // 0..3 (32 rows each)
  const int w_n = w & 3;           // 0..3 (8 nt tiles each)
  const int nb  = blockIdx.x;      // 16
  const int mb  = blockIdx.y;      // 64

  // per-CTA bases; per stage (8 kt16): A = 2048 uint4, B = 8192 uint2 (contiguous)
  const uint4* gA = g_A + (size_t)mb * 32768;
  const uint2* gB = g_B + (size_t)nb * 131072;

  // per-thread load slots: 4 x A (uint4) + 8 x B (uint2-pair) per stage
  // A slot j: entry e = tid + j*512  -> dst sb+buf*STAGE + e*16,  src gA + st*2048 + e
  // B slot j: pair  p = tid + j*512  -> dst sb+buf*STAGE+B_OFF + p*16, src gB + st*8192 + 2p

  auto load_burst = [&](int st){
    uint32_t base = sb + (st & 1) * STAGE_BYTES;
    const uint4* srcA = gA + (size_t)st * 2048;
    #pragma unroll
    for (int j = 0; j < 4; ++j)
      cp16(base + (tid + j * 512) * 16, srcA + tid + j * 512);
    const uint2* srcB = gB + (size_t)st * 8192;
    #pragma unroll
    for (int j = 0; j < 8; ++j)
      cp16(base + B_OFF + (tid + j * 512) * 16, srcB + 2 * (tid + j * 512));
  };

  float acc[2][8][4];
  #pragma unroll
  for (int a = 0; a < 2; ++a)
    #pragma unroll
    for (int b = 0; b < 8; ++b)
      #pragma unroll
      for (int q = 0; q < 4; ++q) acc[a][b][q] = 0.f;

  // prologue: stage 0 in flight
  load_burst(0); cp_commit();

  for (int st = 0; st < NIT; ++st){
    cp_wait<0>();
    __syncthreads();   // stage st ready; all warps done with st-1 -> other buf free

    const uint4* As = (const uint4*)(smem + (st & 1) * STAGE_BYTES);
    const uint2* Bs = (const uint2*)(smem + (st & 1) * STAGE_BYTES + B_OFF);

    const bool pf = (st + 1 < NIT);
    uint32_t nbase = sb + ((st + 1) & 1) * STAGE_BYTES;
    const uint4* nA = gA + (size_t)(st + 1) * 2048;
    const uint2* nB = gB + (size_t)(st + 1) * 8192;

    #pragma unroll
    for (int kt = 0; kt < 8; ++kt){
      // spread next-stage cp.async: pattern 2,1,2,1,2,1,2,1 = 12 per thread
      if (pf){
        if ((kt & 1) == 0){
          int j = kt + (kt >> 1);        // 0,3,6,9 -> issue slots j, j+1
          // slots 0..3 = A, 4..11 = B
          #pragma unroll
          for (int s = 0; s < 2; ++s){
            int sl = j + s;
            if (sl < 4)
              cp16(nbase + (tid + sl * 512) * 16, nA + tid + sl * 512);
            else
              cp16(nbase + B_OFF + (tid + (sl - 4) * 512) * 16, nB + 2 * (tid + (sl - 4) * 512));
          }
        } else {
          int sl = kt + (kt >> 1);       // 1,4,7,10 -> +1 => slots 2,5,8,11
          sl += 1;
          if (sl < 4)
            cp16(nbase + (tid + sl * 512) * 16, nA + tid + sl * 512);
          else
            cp16(nbase + B_OFF + (tid + (sl - 4) * 512) * 16, nB + 2 * (tid + (sl - 4) * 512));
        }
      }

      uint2 bf[8];
      #pragma unroll
      for (int j = 0; j < 8; ++j)
        bf[j] = Bs[(kt * 32 + w_n * 8 + j) * 32 + T];
      uint4 af[2];
      #pragma unroll
      for (int mt = 0; mt < 2; ++mt)
        af[mt] = As[(kt * 8 + w_m * 2 + mt) * 32 + T];
      #pragma unroll
      for (int mt = 0; mt < 2; ++mt)
        #pragma unroll
        for (int j = 0; j < 8; ++j)
          mma16(acc[mt][j], af[mt], bf[j].x, bf[j].y);
    }
    cp_commit();   // one group per stage (empty for last stage is fine)
  }

  // -------- fused LSTM epilogue (register-local: gates g at acc[.][jc*4+g]) --------
  const size_t S = (size_t)B_SZ * 1024;

  float bias[2][4][2];
  #pragma unroll
  for (int jc = 0; jc < 2; ++jc){
    int col = nb * 64 + (w_n * 2 + jc) * 8 + (T & 3) * 2;
    #pragma unroll
    for (int g = 0; g < 4; ++g)
      #pragma unroll
      for (int cc = 0; cc < 2; ++cc)
        bias[jc][g][cc] = bx[g * 1024 + col + cc] + bh[g * 1024 + col + cc];
  }

  #pragma unroll
  for (int mt = 0; mt < 2; ++mt){
    #pragma unroll
    for (int jc = 0; jc < 2; ++jc){
      int col = nb * 64 + (w_n * 2 + jc) * 8 + (T & 3) * 2;
      #pragma unroll
      for (int rr = 0; rr < 2; ++rr){
        int row = mb * 128 + w_m * 32 + mt * 16 + (T >> 2) + rr * 8;
        size_t ro = (size_t)row * 1024 + col;
        float2 cin = *(const float2*)(c + ro);
        float2 o2, h2v, c2;
        #pragma unroll
        for (int cc = 0; cc < 2; ++cc){
          int q = rr * 2 + cc;
          float vi = acc[mt][jc * 4 + 0][q] + bias[jc][0][cc];
          float vf = acc[mt][jc * 4 + 1][q] + bias[jc][1][cc];
          float vg = acc[mt][jc * 4 + 2][q] + bias[jc][2][cc];
          float vo = acc[mt][jc * 4 + 3][q] + bias[jc][3][cc];
          float ig = sigmoidf_(vi);
          float fg = sigmoidf_(vf);
          float gg = tanhf(vg);
          float og = sigmoidf_(vo);
          float cv = (cc == 0) ? cin.x : cin.y;
          float cn = fg * cv + ig * gg;
          float hn = og * tanhf(cn);
          if (cc == 0){ o2.x = og; h2v.x = hn; c2.x = cn; }
          else        { o2.y = og; h2v.y = hn; c2.y = cn; }
        }
        *(float2*)(out + ro)         = o2;    // output gate
        *(float2*)(out + S + ro)     = h2v;   // h_new
        *(float2*)(out + 2 * S + ro) = c2;    // c_new
      }
    }
  }
}

// ---------------- launch ----------------
extern "C" void kernel_launch(void* const* d_in, const int* in_sizes, int n_in,
                              void* d_out, int out_size)
{
  const float* x  = (const float*)d_in[0];
  const float* h  = (const float*)d_in[1];
  const float* c  = (const float*)d_in[2];
  const float* Wx = (const float*)d_in[3];
  const float* Wh = (const float*)d_in[4];
  const float* bx = (const float*)d_in[5];
  const float* bh = (const float*)d_in[6];
  float* out = (float*)d_out;

  cudaFuncSetAttribute(lstm_main,
                       cudaFuncAttributeMaxDynamicSharedMemorySize, SMEM_TOTAL);

  prep_A<<<(B_SZ * KTOT / 8) / 256, 256>>>(x, h);          // 8192 blocks
  prep_B<<<(NOUT * KTOT / 4) / 256, 256>>>(Wx, Wh);        // 8192 blocks
  lstm_main<<<dim3(16, 64), NTHREADS, SMEM_TOTAL>>>(c, bx, bh, out);
}